// round 1
// baseline (speedup 1.0000x reference)
#include <cuda_runtime.h>
#include <math.h>

// Problem constants
#define TK   16384        // total tokens (8 * 2048)
#define DM   1024         // d_model
#define DF   4096         // d_ff
#define NE   8            // experts
#define CAPC 2048         // capacity = ceil(T/E * 1.0)

// ---------------- scratch (static device globals: no allocation) ----------
__device__ float g_expert_in[(size_t)NE * CAPC * DM];   // 64 MB  dispatched tokens
__device__ float g_H[(size_t)NE * CAPC * DF];           // 268 MB hidden activations
__device__ int   g_slot_token[NE * CAPC];               // token occupying slot, -1 empty
__device__ int   g_top1_idx[TK];
__device__ float g_top1_prob[TK];
__device__ float g_Pi[NE];                              // sum of router probs per expert
__device__ float g_zsum;                                // sum of lse^2
__device__ int   g_counts[NE];                          // assigned tokens per expert (uncapped)

// ---------------- init: zero accumulators, empty slots ---------------------
__global__ void init_kernel() {
    int i = blockIdx.x * blockDim.x + threadIdx.x;
    if (i < NE * CAPC) g_slot_token[i] = -1;
    if (i < NE) g_Pi[i] = 0.f;
    if (i == 0) g_zsum = 0.f;
}

// ---------------- router: logits, softmax, top-1, aux stats ---------------
__global__ void router_kernel(const float* __restrict__ x,
                              const float* __restrict__ wr) {
    __shared__ float s_wr[DM * NE];     // 32 KB
    __shared__ float s_pi[NE];
    __shared__ float s_z;
    for (int i = threadIdx.x; i < DM * NE; i += blockDim.x) s_wr[i] = wr[i];
    if (threadIdx.x < NE) s_pi[threadIdx.x] = 0.f;
    if (threadIdx.x == 0) s_z = 0.f;
    __syncthreads();

    int warp = threadIdx.x >> 5, lane = threadIdx.x & 31;
    int gw = blockIdx.x * (blockDim.x >> 5) + warp;
    int nw = gridDim.x * (blockDim.x >> 5);
    for (int t = gw; t < TK; t += nw) {
        const float* xt = x + (size_t)t * DM;
        float acc[NE];
#pragma unroll
        for (int e = 0; e < NE; e++) acc[e] = 0.f;
        for (int k = lane; k < DM; k += 32) {
            float xv = xt[k];
#pragma unroll
            for (int e = 0; e < NE; e++) acc[e] += xv * s_wr[k * NE + e];
        }
#pragma unroll
        for (int e = 0; e < NE; e++) {
#pragma unroll
            for (int off = 16; off; off >>= 1)
                acc[e] += __shfl_xor_sync(0xffffffffu, acc[e], off);
        }
        if (lane == 0) {
            float mx = acc[0]; int mi = 0;
#pragma unroll
            for (int e = 1; e < NE; e++) if (acc[e] > mx) { mx = acc[e]; mi = e; }
            float p[NE]; float se = 0.f;
#pragma unroll
            for (int e = 0; e < NE; e++) { p[e] = expf(acc[e] - mx); se += p[e]; }
            float inv = 1.f / se;
            g_top1_idx[t]  = mi;
            g_top1_prob[t] = inv;             // exp(mx - lse) = 1/se
#pragma unroll
            for (int e = 0; e < NE; e++) atomicAdd(&s_pi[e], p[e] * inv);
            float lse = mx + logf(se);
            atomicAdd(&s_z, lse * lse);
        }
    }
    __syncthreads();
    if (threadIdx.x < NE) atomicAdd(&g_Pi[threadIdx.x], s_pi[threadIdx.x]);
    if (threadIdx.x == 32) atomicAdd(&g_zsum, s_z);
}

// ---------------- FCFS capacity assignment (single block, deterministic) ---
__global__ void assign_kernel() {
    __shared__ int s_cnt[256 * NE];     // 8 KB
    int tid = threadIdx.x;
#pragma unroll
    for (int e = 0; e < NE; e++) s_cnt[tid * NE + e] = 0;
    const int CHUNK = TK / 256;         // 64
    int base = tid * CHUNK;
    for (int i = 0; i < CHUNK; i++) s_cnt[tid * NE + g_top1_idx[base + i]]++;
    __syncthreads();
    if (tid < NE) {                     // exclusive scan per expert + totals
        int run = 0;
        for (int i = 0; i < 256; i++) {
            int v = s_cnt[i * NE + tid];
            s_cnt[i * NE + tid] = run;
            run += v;
        }
        g_counts[tid] = run;
    }
    __syncthreads();
    for (int i = 0; i < CHUNK; i++) {
        int t = base + i;
        int e = g_top1_idx[t];
        int p = s_cnt[tid * NE + e]++;
        if (p < CAPC) g_slot_token[e * CAPC + p] = t;
    }
}

// ---------------- dispatch: gather tokens into expert slots ---------------
__global__ void dispatch_kernel(const float* __restrict__ x) {
    int s = blockIdx.x;
    int t = g_slot_token[s];
    float4* dst = reinterpret_cast<float4*>(g_expert_in + (size_t)s * DM);
    if (t >= 0) {
        const float4* src = reinterpret_cast<const float4*>(x + (size_t)t * DM);
        dst[threadIdx.x] = src[threadIdx.x];
    } else {
        dst[threadIdx.x] = make_float4(0.f, 0.f, 0.f, 0.f);
    }
}

// ---------------- passthrough: out = x (fitted tokens overwritten later) ---
__global__ void copy_out_kernel(const float4* __restrict__ x, float4* __restrict__ out) {
    int i = blockIdx.x * blockDim.x + threadIdx.x;
    if (i < TK * DM / 4) out[i] = x[i];
}

// ---------------- fp32 register-blocked SGEMM ------------------------------
// C[M=16384, N] = A[M, K] * B_e[K, N] with per-expert weights (rows grouped
// by expert, 2048 rows each; BM=128 never crosses an expert boundary).
// EP=0: C = relu(A*W1_e + b1_e) -> g_H
// EP=1: scatter row (slot) -> token with gate scale: out[t] = (A*W2_e + b2_e)*prob[t]
template <int K, int N, int EP>
__global__ __launch_bounds__(256, 2) void sgemm_kernel(
    const float* __restrict__ Bw, const float* __restrict__ bias,
    float* __restrict__ out_arg) {
    constexpr int BM = 128, BN = 128, BK = 8, TM = 8, TN = 8;
    __shared__ float As[BK * BM];
    __shared__ float Bs[BK * BN];

    const float* A = (EP == 0) ? g_expert_in : g_H;
    int tid  = threadIdx.x;
    int cCol = blockIdx.x, cRow = blockIdx.y;
    int expert = (cRow * BM) / CAPC;

    const float* Ap = A + (size_t)cRow * BM * K;
    const float* Bp = Bw + (size_t)expert * K * N + (size_t)cCol * BN;

    int irA = tid >> 1, icA = (tid & 1) * 4;     // 128 rows x 2 float4
    int irB = tid >> 5, icB = (tid & 31) * 4;    // 8 rows x 32 float4
    int tRow = tid >> 4, tCol = tid & 15;

    float acc[TM * TN];
#pragma unroll
    for (int i = 0; i < TM * TN; i++) acc[i] = 0.f;

    for (int k0 = 0; k0 < K; k0 += BK) {
        float4 av = *reinterpret_cast<const float4*>(Ap + (size_t)irA * K + icA);
        As[(icA + 0) * BM + irA] = av.x;
        As[(icA + 1) * BM + irA] = av.y;
        As[(icA + 2) * BM + irA] = av.z;
        As[(icA + 3) * BM + irA] = av.w;
        *reinterpret_cast<float4*>(&Bs[irB * BN + icB]) =
            *reinterpret_cast<const float4*>(Bp + (size_t)irB * N + icB);
        __syncthreads();
        Ap += BK;
        Bp += (size_t)BK * N;
#pragma unroll
        for (int d = 0; d < BK; d++) {
            float regM[TM], regN[TN];
#pragma unroll
            for (int i = 0; i < TM; i += 4)
                *reinterpret_cast<float4*>(&regM[i]) =
                    *reinterpret_cast<const float4*>(&As[d * BM + tRow * TM + i]);
#pragma unroll
            for (int j = 0; j < TN; j += 4)
                *reinterpret_cast<float4*>(&regN[j]) =
                    *reinterpret_cast<const float4*>(&Bs[d * BN + tCol * TN + j]);
#pragma unroll
            for (int i = 0; i < TM; i++)
#pragma unroll
                for (int j = 0; j < TN; j++)
                    acc[i * TN + j] += regM[i] * regN[j];
        }
        __syncthreads();
    }

    const float* bp = bias + expert * N + cCol * BN + tCol * TN;
#pragma unroll
    for (int i = 0; i < TM; i++) {
        int row = cRow * BM + tRow * TM + i;
        if (EP == 1) {
            int t = g_slot_token[row];
            if (t < 0) continue;                 // empty capacity slot
            float sc = g_top1_prob[t];
            float* orow = out_arg + (size_t)t * N + cCol * BN + tCol * TN;
#pragma unroll
            for (int j = 0; j < TN; j += 4) {
                float4 v;
                v.x = (acc[i * TN + j + 0] + bp[j + 0]) * sc;
                v.y = (acc[i * TN + j + 1] + bp[j + 1]) * sc;
                v.z = (acc[i * TN + j + 2] + bp[j + 2]) * sc;
                v.w = (acc[i * TN + j + 3] + bp[j + 3]) * sc;
                *reinterpret_cast<float4*>(orow + j) = v;
            }
        } else {
            float* orow = g_H + (size_t)row * N + cCol * BN + tCol * TN;
#pragma unroll
            for (int j = 0; j < TN; j += 4) {
                float4 v;
                v.x = fmaxf(acc[i * TN + j + 0] + bp[j + 0], 0.f);
                v.y = fmaxf(acc[i * TN + j + 1] + bp[j + 1], 0.f);
                v.z = fmaxf(acc[i * TN + j + 2] + bp[j + 2], 0.f);
                v.w = fmaxf(acc[i * TN + j + 3] + bp[j + 3], 0.f);
                *reinterpret_cast<float4*>(orow + j) = v;
            }
        }
    }
}

// ---------------- aux loss scalar ------------------------------------------
__global__ void finalize_kernel(float* out_scalar) {
    float dot = 0.f;
#pragma unroll
    for (int e = 0; e < NE; e++)
        dot += ((float)g_counts[e] / (float)TK) * (g_Pi[e] / (float)TK);
    float aux = 0.01f * (float)NE * dot + 0.001f * (g_zsum / (float)TK);
    *out_scalar = aux;
}

// ---------------- launch ----------------------------------------------------
extern "C" void kernel_launch(void* const* d_in, const int* in_sizes, int n_in,
                              void* d_out, int out_size) {
    const float* x  = (const float*)d_in[0];   // [8,2048,1024]
    const float* wr = (const float*)d_in[1];   // [1024,8]
    const float* w1 = (const float*)d_in[2];   // [8,1024,4096]
    const float* b1 = (const float*)d_in[3];   // [8,4096]
    const float* w2 = (const float*)d_in[4];   // [8,4096,1024]
    const float* b2 = (const float*)d_in[5];   // [8,1024]
    float* out = (float*)d_out;

    init_kernel<<<(NE * CAPC + 255) / 256, 256>>>();
    router_kernel<<<256, 256>>>(x, wr);
    assign_kernel<<<1, 256>>>();
    dispatch_kernel<<<NE * CAPC, 256>>>(x);
    copy_out_kernel<<<(TK * DM / 4 + 255) / 256, 256>>>(
        (const float4*)x, (float4*)d_out);

    // GEMM1: H = relu(Xe * W1 + b1)   [16384 x 4096], K=1024
    sgemm_kernel<DM, DF, 0><<<dim3(DF / 128, TK / 128), 256>>>(w1, b1, nullptr);
    // GEMM2: out[t] = (H * W2 + b2) * prob  [scatter], K=4096
    sgemm_kernel<DF, DM, 1><<<dim3(DM / 128, TK / 128), 256>>>(w2, b2, out);

    if (out_size > TK * DM)
        finalize_kernel<<<1, 1>>>(out + (size_t)TK * DM);
}

// round 3
// speedup vs baseline: 3.7685x; 3.7685x over previous
#include <cuda_runtime.h>
#include <math.h>
#include <stdint.h>

// Problem constants
#define TK   16384        // total tokens (8 * 2048)
#define DM   1024         // d_model
#define DF   4096         // d_ff
#define NE   8            // experts
#define CAPC 2048         // capacity

// GEMM tiling (Ampere-style tf32 mma.sync path — compute_103-safe)
#define BM   128
#define BN   256
#define BKT  32                         // K per stage: 32 fp32 = 128B = SW128 row
#define NS   3                          // cp.async pipeline stages
#define A_BYTES (BM * BKT * 4)          // 16384
#define B_BYTES (BN * BKT * 4)          // 32768
#define STAGE_BYTES (A_BYTES + B_BYTES) // 49152
#define SMEM_TOTAL (NS * STAGE_BYTES)   // 147456

// ---------------- scratch ---------------------------------------------------
__device__ float g_expert_in[(size_t)NE * CAPC * DM];   // tf32-rounded dispatched tokens
__device__ float g_H[(size_t)TK * DF];                  // tf32-rounded hidden acts
__device__ float g_W1t[(size_t)NE * DF * DM];           // W1^T [E][4096][1024]
__device__ float g_W2t[(size_t)NE * DM * DF];           // W2^T [E][1024][4096]
__device__ int   g_slot_token[NE * CAPC];
__device__ int   g_top1_idx[TK];
__device__ float g_top1_prob[TK];
__device__ float g_Pi[NE];
__device__ float g_zsum;
__device__ int   g_counts[NE];

// ---------------- helpers ---------------------------------------------------
__device__ __forceinline__ uint32_t smem_u32(const void* p) {
    uint32_t a;
    asm("{ .reg .u64 t; cvta.to.shared.u64 t, %1; cvt.u32.u64 %0, t; }" : "=r"(a) : "l"(p));
    return a;
}
__device__ __forceinline__ float tf32r(float x) {
    uint32_t b;
    asm("cvt.rna.tf32.f32 %0, %1;" : "=r"(b) : "f"(x));
    return __uint_as_float(b);
}
__device__ __forceinline__ void cp16(uint32_t sm, const void* g) {
    asm volatile("cp.async.cg.shared.global [%0], [%1], 16;" :: "r"(sm), "l"(g));
}
#define CP_COMMIT() asm volatile("cp.async.commit_group;" ::: "memory")
#define CP_WAIT(n)  asm volatile("cp.async.wait_group %0;" :: "n"(n) : "memory")

__device__ __forceinline__ void ldsm4(uint32_t& r0, uint32_t& r1, uint32_t& r2,
                                      uint32_t& r3, uint32_t addr) {
    asm volatile("ldmatrix.sync.aligned.m8n8.x4.shared.b16 {%0,%1,%2,%3}, [%4];"
                 : "=r"(r0), "=r"(r1), "=r"(r2), "=r"(r3) : "r"(addr));
}
__device__ __forceinline__ void mma_tf32(float* d, const uint32_t* a, const uint32_t* b) {
    asm volatile(
        "mma.sync.aligned.m16n8k8.row.col.f32.tf32.tf32.f32 "
        "{%0,%1,%2,%3}, {%4,%5,%6,%7}, {%8,%9}, {%0,%1,%2,%3};"
        : "+f"(d[0]), "+f"(d[1]), "+f"(d[2]), "+f"(d[3])
        : "r"(a[0]), "r"(a[1]), "r"(a[2]), "r"(a[3]), "r"(b[0]), "r"(b[1]));
}

// ---------------- init ------------------------------------------------------
__global__ void init_kernel() {
    int i = blockIdx.x * blockDim.x + threadIdx.x;
    if (i < NE * CAPC) g_slot_token[i] = -1;
    if (i < NE) g_Pi[i] = 0.f;
    if (i == 0) g_zsum = 0.f;
}

// ---------------- router ----------------------------------------------------
__global__ void router_kernel(const float* __restrict__ x,
                              const float* __restrict__ wr) {
    __shared__ float s_wr[DM * NE];
    __shared__ float s_pi[NE];
    __shared__ float s_z;
    for (int i = threadIdx.x; i < DM * NE; i += blockDim.x) s_wr[i] = wr[i];
    if (threadIdx.x < NE) s_pi[threadIdx.x] = 0.f;
    if (threadIdx.x == 0) s_z = 0.f;
    __syncthreads();

    int warp = threadIdx.x >> 5, lane = threadIdx.x & 31;
    int gw = blockIdx.x * (blockDim.x >> 5) + warp;
    int nw = gridDim.x * (blockDim.x >> 5);
    for (int t = gw; t < TK; t += nw) {
        const float* xt = x + (size_t)t * DM;
        float acc[NE];
#pragma unroll
        for (int e = 0; e < NE; e++) acc[e] = 0.f;
        for (int k = lane; k < DM; k += 32) {
            float xv = xt[k];
#pragma unroll
            for (int e = 0; e < NE; e++) acc[e] += xv * s_wr[k * NE + e];
        }
#pragma unroll
        for (int e = 0; e < NE; e++) {
#pragma unroll
            for (int off = 16; off; off >>= 1)
                acc[e] += __shfl_xor_sync(0xffffffffu, acc[e], off);
        }
        if (lane == 0) {
            float mx = acc[0]; int mi = 0;
#pragma unroll
            for (int e = 1; e < NE; e++) if (acc[e] > mx) { mx = acc[e]; mi = e; }
            float p[NE]; float se = 0.f;
#pragma unroll
            for (int e = 0; e < NE; e++) { p[e] = expf(acc[e] - mx); se += p[e]; }
            float inv = 1.f / se;
            g_top1_idx[t]  = mi;
            g_top1_prob[t] = inv;
#pragma unroll
            for (int e = 0; e < NE; e++) atomicAdd(&s_pi[e], p[e] * inv);
            float lse = mx + logf(se);
            atomicAdd(&s_z, lse * lse);
        }
    }
    __syncthreads();
    if (threadIdx.x < NE) atomicAdd(&g_Pi[threadIdx.x], s_pi[threadIdx.x]);
    if (threadIdx.x == 32) atomicAdd(&g_zsum, s_z);
}

// ---------------- FCFS capacity assignment ---------------------------------
__global__ void assign_kernel() {
    __shared__ int s_cnt[256 * NE];
    int tid = threadIdx.x;
#pragma unroll
    for (int e = 0; e < NE; e++) s_cnt[tid * NE + e] = 0;
    const int CHUNK = TK / 256;
    int base = tid * CHUNK;
    for (int i = 0; i < CHUNK; i++) s_cnt[tid * NE + g_top1_idx[base + i]]++;
    __syncthreads();
    if (tid < NE) {
        int run = 0;
        for (int i = 0; i < 256; i++) {
            int v = s_cnt[i * NE + tid];
            s_cnt[i * NE + tid] = run;
            run += v;
        }
        g_counts[tid] = run;
    }
    __syncthreads();
    for (int i = 0; i < CHUNK; i++) {
        int t = base + i;
        int e = g_top1_idx[t];
        int p = s_cnt[tid * NE + e]++;
        if (p < CAPC) g_slot_token[e * CAPC + p] = t;
    }
}

// ---------------- dispatch (tf32-rounded) -----------------------------------
__global__ void dispatch_kernel(const float* __restrict__ x) {
    int s = blockIdx.x;
    int t = g_slot_token[s];
    float4* dst = reinterpret_cast<float4*>(g_expert_in + (size_t)s * DM);
    if (t >= 0) {
        float4 v = reinterpret_cast<const float4*>(x + (size_t)t * DM)[threadIdx.x];
        v.x = tf32r(v.x); v.y = tf32r(v.y); v.z = tf32r(v.z); v.w = tf32r(v.w);
        dst[threadIdx.x] = v;
    } else {
        dst[threadIdx.x] = make_float4(0.f, 0.f, 0.f, 0.f);
    }
}

// ---------------- passthrough copy ------------------------------------------
__global__ void copy_out_kernel(const float4* __restrict__ x, float4* __restrict__ out) {
    int i = blockIdx.x * blockDim.x + threadIdx.x;
    if (i < TK * DM / 4) out[i] = x[i];
}

// ---------------- weight transpose [E][K][N] -> [E][N][K] (tf32-rounded) ----
__global__ void transpose_kernel(const float* __restrict__ src, float* __restrict__ dst,
                                 int K, int N) {
    __shared__ float tile[32][33];
    int e = blockIdx.z;
    int k0 = blockIdx.y * 32, n0 = blockIdx.x * 32;
    src += (size_t)e * K * N;
    dst += (size_t)e * N * K;
#pragma unroll
    for (int i = threadIdx.y; i < 32; i += 8)
        tile[i][threadIdx.x] = src[(size_t)(k0 + i) * N + n0 + threadIdx.x];
    __syncthreads();
#pragma unroll
    for (int i = threadIdx.y; i < 32; i += 8)
        dst[(size_t)(n0 + i) * K + k0 + threadIdx.x] = tf32r(tile[threadIdx.x][i]);
}

// ---------------- tf32 mma.sync GEMM ----------------------------------------
// C[16384, NTOT] = A[16384, K] * Bt_e[NTOT, K]^T  (per-expert weights)
// CTA 128x256; 8 warps in 2x4 grid, each 64x64.
// EP=0: H = relu(Xe*W1+b1) tf32-rounded; EP=1: scatter (H*W2+b2)*prob -> out
template <int K, int NTOT, int EP>
__global__ __launch_bounds__(256, 1) void moe_gemm(
    const float* __restrict__ Bt, const float* __restrict__ bias,
    float* __restrict__ outp) {
    extern __shared__ char smem[];
    const uint32_t sb = smem_u32(smem);
    const int tid = threadIdx.x, wid = tid >> 5, lane = tid & 31;
    constexpr int KT = K / BKT;

    const float* A = (EP == 0) ? g_expert_in : g_H;
    const int cCol = blockIdx.x, cRow = blockIdx.y;
    const int expert = cRow >> 4;                 // 2048 rows / 128 per expert
    const int aRow0 = cRow * BM;
    const int bRow0 = expert * NTOT + cCol * BN;
    const int warpM = (wid >> 2) * 64;            // 0 or 64
    const int warpN = (wid & 3) * 64;             // 0..192

    // cp.async per-thread pattern: 16B chunks, swizzled smem targets
    // A: 4 chunks, B: 8 chunks per stage
    uint32_t swzA[4], swzB[8];
    const float* gA[4];
    const float* gB[8];
#pragma unroll
    for (int i = 0; i < 4; i++) {
        int q = tid + i * 256, r = q >> 3, c = q & 7;
        swzA[i] = r * 128 + ((c ^ (r & 7)) * 16);
        gA[i] = A + (size_t)(aRow0 + r) * K + c * 4;
    }
#pragma unroll
    for (int i = 0; i < 8; i++) {
        int q = tid + i * 256, r = q >> 3, c = q & 7;
        swzB[i] = r * 128 + ((c ^ (r & 7)) * 16);
        gB[i] = Bt + (size_t)(bRow0 + r) * K + c * 4;
    }

#define LOAD_STAGE(s, kI) do {                                              \
    uint32_t _stA = sb + (s) * STAGE_BYTES;                                 \
    uint32_t _stB = _stA + A_BYTES;                                         \
    int _k0 = (kI) * BKT;                                                   \
    _Pragma("unroll")                                                       \
    for (int _i = 0; _i < 4; _i++) cp16(_stA + swzA[_i], gA[_i] + _k0);     \
    _Pragma("unroll")                                                       \
    for (int _i = 0; _i < 8; _i++) cp16(_stB + swzB[_i], gB[_i] + _k0);     \
} while (0)

    // ldmatrix per-lane address components
    const int rowLow = lane & 7;                  // row % 8 (swizzle selector)
    const int tau = lane >> 3;                    // tile index within x4
    // A tiles: t0 rows+0 ch+0, t1 rows+8 ch+0, t2 rows+0 ch+1, t3 rows+8 ch+1
    const int rA = warpM + (tau & 1) * 8 + rowLow;
    const int hiA = tau >> 1;
    // B tiles: t0 rows+0 ch+0, t1 rows+0 ch+1, t2 rows+8 ch+0, t3 rows+8 ch+1
    const int rB = warpN + (tau >> 1) * 8 + rowLow;
    const int hiB = tau & 1;

    float acc[4][8][4];
#pragma unroll
    for (int m = 0; m < 4; m++)
#pragma unroll
        for (int n = 0; n < 8; n++)
#pragma unroll
            for (int v = 0; v < 4; v++) acc[m][n][v] = 0.f;

    // prologue: fill NS-1 stages
#pragma unroll
    for (int p = 0; p < NS - 1; p++) { LOAD_STAGE(p, p); CP_COMMIT(); }

    for (int kb = 0; kb < KT; kb++) {
        int kp = kb + NS - 1;
        if (kp < KT) LOAD_STAGE(kp % NS, kp);
        CP_COMMIT();
        CP_WAIT(NS - 2);
        __syncthreads();

        const uint32_t aBase = sb + (kb % NS) * STAGE_BYTES;
        const uint32_t bBase = aBase + A_BYTES;
#pragma unroll
        for (int ks = 0; ks < 4; ks++) {
            uint32_t af[4][4];
#pragma unroll
            for (int mt = 0; mt < 4; mt++) {
                uint32_t addr = aBase + (rA + mt * 16) * 128 +
                                (((2 * ks + hiA) ^ rowLow) * 16);
                ldsm4(af[mt][0], af[mt][1], af[mt][2], af[mt][3], addr);
            }
            uint32_t bf[4][4];                    // pair p covers n-tiles 2p,2p+1
#pragma unroll
            for (int p = 0; p < 4; p++) {
                uint32_t addr = bBase + (rB + p * 16) * 128 +
                                (((2 * ks + hiB) ^ rowLow) * 16);
                ldsm4(bf[p][0], bf[p][1], bf[p][2], bf[p][3], addr);
            }
#pragma unroll
            for (int mt = 0; mt < 4; mt++)
#pragma unroll
                for (int nt = 0; nt < 8; nt++)
                    mma_tf32(acc[mt][nt], af[mt], &bf[nt >> 1][(nt & 1) * 2]);
        }
        __syncthreads();
    }
#undef LOAD_STAGE

    // ---------------- epilogue (registers -> gmem) ----------------
    const int colW = cCol * BN + warpN;
#pragma unroll
    for (int mt = 0; mt < 4; mt++) {
        int r1 = aRow0 + warpM + mt * 16 + (lane >> 2);
        int r2 = r1 + 8;
        int tok1 = 0, tok2 = 0; float sc1 = 0.f, sc2 = 0.f;
        if (EP == 1) {
            tok1 = g_slot_token[r1];
            tok2 = g_slot_token[r2];
            if (tok1 >= 0) sc1 = g_top1_prob[tok1];
            if (tok2 >= 0) sc2 = g_top1_prob[tok2];
        }
#pragma unroll
        for (int nt = 0; nt < 8; nt++) {
            int col = colW + nt * 8 + 2 * (lane & 3);
            const float* bp = bias + expert * NTOT + col;
            float b0 = bp[0], b1 = bp[1];
            if (EP == 0) {
                float2 v1, v2;
                v1.x = tf32r(fmaxf(acc[mt][nt][0] + b0, 0.f));
                v1.y = tf32r(fmaxf(acc[mt][nt][1] + b1, 0.f));
                v2.x = tf32r(fmaxf(acc[mt][nt][2] + b0, 0.f));
                v2.y = tf32r(fmaxf(acc[mt][nt][3] + b1, 0.f));
                *reinterpret_cast<float2*>(g_H + (size_t)r1 * NTOT + col) = v1;
                *reinterpret_cast<float2*>(g_H + (size_t)r2 * NTOT + col) = v2;
            } else {
                if (tok1 >= 0) {
                    float2 v;
                    v.x = (acc[mt][nt][0] + b0) * sc1;
                    v.y = (acc[mt][nt][1] + b1) * sc1;
                    *reinterpret_cast<float2*>(outp + (size_t)tok1 * NTOT + col) = v;
                }
                if (tok2 >= 0) {
                    float2 v;
                    v.x = (acc[mt][nt][2] + b0) * sc2;
                    v.y = (acc[mt][nt][3] + b1) * sc2;
                    *reinterpret_cast<float2*>(outp + (size_t)tok2 * NTOT + col) = v;
                }
            }
        }
    }
}

// ---------------- aux loss --------------------------------------------------
__global__ void finalize_kernel(float* out_scalar) {
    float dot = 0.f;
#pragma unroll
    for (int e = 0; e < NE; e++)
        dot += ((float)g_counts[e] / (float)TK) * (g_Pi[e] / (float)TK);
    float aux = 0.01f * (float)NE * dot + 0.001f * (g_zsum / (float)TK);
    *out_scalar = aux;
}

// ---------------- launch ----------------------------------------------------
extern "C" void kernel_launch(void* const* d_in, const int* in_sizes, int n_in,
                              void* d_out, int out_size) {
    const float* x  = (const float*)d_in[0];
    const float* wr = (const float*)d_in[1];
    const float* w1 = (const float*)d_in[2];
    const float* b1 = (const float*)d_in[3];
    const float* w2 = (const float*)d_in[4];
    const float* b2 = (const float*)d_in[5];
    float* out = (float*)d_out;

    cudaFuncSetAttribute(moe_gemm<DM, DF, 0>,
                         cudaFuncAttributeMaxDynamicSharedMemorySize, SMEM_TOTAL);
    cudaFuncSetAttribute(moe_gemm<DF, DM, 1>,
                         cudaFuncAttributeMaxDynamicSharedMemorySize, SMEM_TOTAL);

    float* w1t; cudaGetSymbolAddress((void**)&w1t, g_W1t);
    float* w2t; cudaGetSymbolAddress((void**)&w2t, g_W2t);

    init_kernel<<<(NE * CAPC + 255) / 256, 256>>>();
    router_kernel<<<256, 256>>>(x, wr);
    assign_kernel<<<1, 256>>>();
    dispatch_kernel<<<NE * CAPC, 256>>>(x);
    copy_out_kernel<<<(TK * DM / 4 + 255) / 256, 256>>>(
        (const float4*)x, (float4*)d_out);

    transpose_kernel<<<dim3(DF / 32, DM / 32, NE), dim3(32, 8)>>>(w1, w1t, DM, DF);
    transpose_kernel<<<dim3(DM / 32, DF / 32, NE), dim3(32, 8)>>>(w2, w2t, DF, DM);

    // GEMM1: H = relu(Xe * W1 + b1)   [16384 x 4096], K=1024
    moe_gemm<DM, DF, 0><<<dim3(DF / BN, TK / BM), 256, SMEM_TOTAL>>>(w1t, b1, nullptr);
    // GEMM2: out[t] = (H * W2 + b2) * prob, K=4096
    moe_gemm<DF, DM, 1><<<dim3(DM / BN, TK / BM), 256, SMEM_TOTAL>>>(w2t, b2, out);

    if (out_size > TK * DM)
        finalize_kernel<<<1, 1>>>(out + (size_t)TK * DM);
}